// round 8
// baseline (speedup 1.0000x reference)
#include <cuda_runtime.h>
#include <cuda_fp16.h>

#define OUT_DIM 11008
#define IN_DIM  4096
#define MTOK    2048

// ---------------- scratch (device globals; no runtime allocation) ----------------
__device__ __half g_Wh[(size_t)OUT_DIM * IN_DIM];
__device__ __half g_Xh[(size_t)MTOK * IN_DIM];

static __device__ __forceinline__ unsigned smem_u32(const void* p) {
    return (unsigned)__cvta_generic_to_shared(p);
}

static __device__ __forceinline__ unsigned h2_as_u32(__half2 h) {
    return *reinterpret_cast<unsigned*>(&h);
}

#define CP16(dst_u32, src_ptr) \
    asm volatile("cp.async.cg.shared.global [%0], [%1], 16;" \
                 :: "r"(dst_u32), "l"(src_ptr) : "memory")

#define LDSM4(R, ADDR) \
    asm volatile("ldmatrix.sync.aligned.m8n8.x4.shared.b16 {%0,%1,%2,%3}, [%4];" \
                 : "=r"((R)[0]), "=r"((R)[1]), "=r"((R)[2]), "=r"((R)[3]) : "r"(ADDR))

// fp16-accumulate MMA: d = a*b + c, all f16. First step of an iter passes c=0.
#define MMA16816_F16_INIT(D, A, B0, B1) \
    asm volatile("mma.sync.aligned.m16n8k16.row.col.f16.f16.f16.f16 " \
                 "{%0,%1}, {%2,%3,%4,%5}, {%6,%7}, {%8,%8};" \
                 : "=r"((D)[0]), "=r"((D)[1]) \
                 : "r"((A)[0]), "r"((A)[1]), "r"((A)[2]), "r"((A)[3]), \
                   "r"(B0), "r"(B1), "r"(0u))

#define MMA16816_F16_ACC(D, A, B0, B1) \
    asm volatile("mma.sync.aligned.m16n8k16.row.col.f16.f16.f16.f16 " \
                 "{%0,%1}, {%2,%3,%4,%5}, {%6,%7}, {%0,%1};" \
                 : "+r"((D)[0]), "+r"((D)[1]) \
                 : "r"((A)[0]), "r"((A)[1]), "r"((A)[2]), "r"((A)[3]), \
                   "r"(B0), "r"(B1))

// ---------------- kernel 1: dequant packed int4 -> fp16 W (wide) ----------------
// each int32 of base_packed holds one byte-value: low nibble -> col 2j, high -> 2j+1
__global__ void dequant_kernel(const int* __restrict__ packed,
                               const float* __restrict__ scales) {
    size_t i = (size_t)blockIdx.x * blockDim.x + threadIdx.x;   // uint4 index
    const size_t n = (size_t)OUT_DIM * (IN_DIM / 2) / 4;
    if (i >= n) return;
    uint4 p = reinterpret_cast<const uint4*>(packed)[i];
    int row = (int)((i * 4) >> 11);          // IN_DIM/2 = 2048 per row, 4 | 2048
    float s = scales[row];
    uint4 o;
    {
        int v = (int)p.x;
        o.x = h2_as_u32(__floats2half2_rn((float)((v & 15) - 8) * s,
                                          (float)(((v >> 4) & 15) - 8) * s));
        v = (int)p.y;
        o.y = h2_as_u32(__floats2half2_rn((float)((v & 15) - 8) * s,
                                          (float)(((v >> 4) & 15) - 8) * s));
        v = (int)p.z;
        o.z = h2_as_u32(__floats2half2_rn((float)((v & 15) - 8) * s,
                                          (float)(((v >> 4) & 15) - 8) * s));
        v = (int)p.w;
        o.w = h2_as_u32(__floats2half2_rn((float)((v & 15) - 8) * s,
                                          (float)(((v >> 4) & 15) - 8) * s));
    }
    reinterpret_cast<uint4*>(g_Wh)[i] = o;
}

// ---------------- kernel 2: sparse scatter-add (native fp16 atomics) ----------------
__global__ void scatter_kernel(const float* __restrict__ vals,
                               const int* __restrict__ rows,
                               const int* __restrict__ cols, int nnz) {
    int i = blockIdx.x * blockDim.x + threadIdx.x;
    if (i >= nnz) return;
    atomicAdd(&g_Wh[(size_t)rows[i] * IN_DIM + cols[i]], __float2half(vals[i]));
}

// ---------------- kernel 3: convert x -> fp16 (wide) ----------------
__global__ void convert_x_kernel(const float* __restrict__ x) {
    size_t i = (size_t)blockIdx.x * blockDim.x + threadIdx.x;   // 8-elem unit
    const size_t n8 = (size_t)MTOK * IN_DIM / 8;
    if (i >= n8) return;
    float4 v0 = reinterpret_cast<const float4*>(x)[2 * i + 0];
    float4 v1 = reinterpret_cast<const float4*>(x)[2 * i + 1];
    uint4 o;
    o.x = h2_as_u32(__floats2half2_rn(v0.x, v0.y));
    o.y = h2_as_u32(__floats2half2_rn(v0.z, v0.w));
    o.z = h2_as_u32(__floats2half2_rn(v1.x, v1.y));
    o.w = h2_as_u32(__floats2half2_rn(v1.z, v1.w));
    reinterpret_cast<uint4*>(g_Xh)[i] = o;
}

// ---------------- kernel 4: mma.sync fp16 GEMM, fp16-accum + fp32 promote ------
// out = Xh * Wh^T. CTA tile 128x128, 8 warps (2x4), warp tile 64x32, K-tile 64.
// Within one K-tile: 4 x k16 MMAs accumulate in fp16 (partial sums over K=64),
// then promoted into persistent fp32 accumulators. 3-stage cp.async (32KB/stage).
#define KTILE 64
#define A_BYTES 16384
#define STAGE_BYTES 32768
#define N_ITERS (IN_DIM / KTILE)   // 64

#define SWZ(r_, c_) ((r_) * 128 + ((((c_) ^ ((r_) & 7))) << 4))

__global__ void __launch_bounds__(256, 2) gemm_kernel(float* __restrict__ out) {
    extern __shared__ char smem[];
    const int tid  = threadIdx.x;
    const int lane = tid & 31;
    const int w    = tid >> 5;
    const int wm   = w & 1;        // 0..1 : 64-row half (M)
    const int wn   = w >> 1;       // 0..3 : 32-col quarter (N)
    const int mt   = blockIdx.x;   // 0..15
    const int nt   = blockIdx.y;   // 0..85

    float c[4][4][4];
    #pragma unroll
    for (int mi = 0; mi < 4; ++mi)
        #pragma unroll
        for (int ni = 0; ni < 4; ++ni)
            #pragma unroll
            for (int q = 0; q < 4; ++q) c[mi][ni][q] = 0.f;

    const int lr = tid >> 3;             // 0..31
    const int lc = tid & 7;              // chunk 0..7
    const unsigned sbase = smem_u32(smem);

    const __half* Ab = g_Xh + (size_t)mt * 128 * IN_DIM;
    const __half* Bb = g_Wh + (size_t)nt * 128 * IN_DIM;

    #define LOAD_TILE(it_) do {                                                   \
        int k0_ = (it_) << 6;                                                     \
        unsigned sa_ = sbase + ((it_) % 3) * STAGE_BYTES;                         \
        unsigned sb_ = sa_ + A_BYTES;                                             \
        const __half* ap_ = Ab + k0_ + lc * 8;                                    \
        const __half* bp_ = Bb + k0_ + lc * 8;                                    \
        _Pragma("unroll")                                                         \
        for (int p_ = 0; p_ < 4; ++p_) {                                          \
            int r_ = lr + p_ * 32;                                                \
            CP16(sa_ + SWZ(r_, lc), ap_ + (size_t)r_ * IN_DIM);                   \
            CP16(sb_ + SWZ(r_, lc), bp_ + (size_t)r_ * IN_DIM);                   \
        }                                                                         \
    } while (0)

    LOAD_TILE(0);
    asm volatile("cp.async.commit_group;" ::: "memory");
    LOAD_TILE(1);
    asm volatile("cp.async.commit_group;" ::: "memory");

    for (int it = 0; it < N_ITERS; ++it) {
        asm volatile("cp.async.wait_group 1;" ::: "memory");
        __syncthreads();

        unsigned sa = sbase + (it % 3) * STAGE_BYTES;
        unsigned sb = sa + A_BYTES;

        unsigned c16[4][4][2];           // fp16 working accum, live one iter

        #pragma unroll
        for (int kk = 0; kk < 4; ++kk) {
            unsigned a[4][4], b[2][4];
            #pragma unroll
            for (int mi = 0; mi < 4; ++mi) {
                int r = wm * 64 + mi * 16 + (lane & 15);
                int ci = 2 * kk + (lane >> 4);
                LDSM4(a[mi], sa + SWZ(r, ci));
            }
            #pragma unroll
            for (int nj = 0; nj < 2; ++nj) {
                int r = wn * 32 + nj * 16 + (lane & 7) + ((lane >> 4) << 3);
                int ci = 2 * kk + ((lane >> 3) & 1);
                LDSM4(b[nj], sb + SWZ(r, ci));
            }

            if (kk == 0) {   // prefetch stage (it+2)%3 while kk=0 math runs
                if (it + 2 < N_ITERS) LOAD_TILE(it + 2);
                asm volatile("cp.async.commit_group;" ::: "memory");
            }

            #pragma unroll
            for (int mi = 0; mi < 4; ++mi)
                #pragma unroll
                for (int ni = 0; ni < 4; ++ni) {
                    unsigned b0 = b[ni >> 1][(ni & 1) * 2 + 0];
                    unsigned b1 = b[ni >> 1][(ni & 1) * 2 + 1];
                    if (kk == 0) MMA16816_F16_INIT(c16[mi][ni], a[mi], b0, b1);
                    else         MMA16816_F16_ACC (c16[mi][ni], a[mi], b0, b1);
                }
        }

        // promote K=64 fp16 partial sums into fp32 accumulators
        #pragma unroll
        for (int mi = 0; mi < 4; ++mi)
            #pragma unroll
            for (int ni = 0; ni < 4; ++ni) {
                float2 p0 = __half22float2(*reinterpret_cast<__half2*>(&c16[mi][ni][0]));
                float2 p1 = __half22float2(*reinterpret_cast<__half2*>(&c16[mi][ni][1]));
                c[mi][ni][0] += p0.x;
                c[mi][ni][1] += p0.y;
                c[mi][ni][2] += p1.x;
                c[mi][ni][3] += p1.y;
            }
        // no trailing barrier: next iter's top barrier provides ordering
    }

    // ---- epilogue: direct fp32 stores ----
    const int r0 = mt * 128 + wm * 64 + (lane >> 2);
    const int c0 = nt * 128 + wn * 32 + (lane & 3) * 2;
    #pragma unroll
    for (int mi = 0; mi < 4; ++mi) {
        #pragma unroll
        for (int ni = 0; ni < 4; ++ni) {
            size_t rowA = (size_t)(r0 + mi * 16) * OUT_DIM + c0 + ni * 8;
            size_t rowB = rowA + (size_t)8 * OUT_DIM;
            float2 v01; v01.x = c[mi][ni][0]; v01.y = c[mi][ni][1];
            float2 v23; v23.x = c[mi][ni][2]; v23.y = c[mi][ni][3];
            *reinterpret_cast<float2*>(out + rowA) = v01;
            *reinterpret_cast<float2*>(out + rowB) = v23;
        }
    }
}

// ---------------- launcher ----------------
extern "C" void kernel_launch(void* const* d_in, const int* in_sizes, int n_in,
                              void* d_out, int out_size) {
    const float* x      = (const float*)d_in[0];
    const float* scales = (const float*)d_in[1];
    const float* vals   = (const float*)d_in[2];
    const int*   packed = (const int*)d_in[3];
    const int*   rows   = (const int*)d_in[4];
    const int*   cols   = (const int*)d_in[5];
    float* out = (float*)d_out;
    int nnz = in_sizes[2];

    // idempotent, non-stream API: safe under graph capture
    cudaFuncSetAttribute(gemm_kernel,
                         cudaFuncAttributeMaxDynamicSharedMemorySize,
                         3 * STAGE_BYTES);

    {
        size_t n = (size_t)OUT_DIM * (IN_DIM / 2) / 4;
        dequant_kernel<<<(unsigned)((n + 255) / 256), 256>>>(packed, scales);
    }
    scatter_kernel<<<(nnz + 255) / 256, 256>>>(vals, rows, cols, nnz);
    {
        size_t n8 = (size_t)MTOK * IN_DIM / 8;
        convert_x_kernel<<<(unsigned)((n8 + 255) / 256), 256>>>(x);
    }
    {
        dim3 grid(MTOK / 128, OUT_DIM / 128);  // (16, 86); x fastest -> B n-tile L2 reuse
        gemm_kernel<<<grid, 256, 3 * STAGE_BYTES>>>(out);
    }
}

// round 9
// speedup vs baseline: 1.2232x; 1.2232x over previous
#include <cuda_runtime.h>
#include <cuda_fp16.h>

#define OUT_DIM 11008
#define IN_DIM  4096
#define MTOK    2048

// ---------------- scratch (device globals; no runtime allocation) ----------------
__device__ __half g_Wh[(size_t)OUT_DIM * IN_DIM];
__device__ __half g_Xh[(size_t)MTOK * IN_DIM];

static __device__ __forceinline__ unsigned smem_u32(const void* p) {
    return (unsigned)__cvta_generic_to_shared(p);
}

static __device__ __forceinline__ unsigned h2_as_u32(__half2 h) {
    return *reinterpret_cast<unsigned*>(&h);
}

#define CP16(dst_u32, src_ptr) \
    asm volatile("cp.async.cg.shared.global [%0], [%1], 16;" \
                 :: "r"(dst_u32), "l"(src_ptr) : "memory")

#define LDSM4(R, ADDR) \
    asm volatile("ldmatrix.sync.aligned.m8n8.x4.shared.b16 {%0,%1,%2,%3}, [%4];" \
                 : "=r"((R)[0]), "=r"((R)[1]), "=r"((R)[2]), "=r"((R)[3]) : "r"(ADDR))

#define MMA16816(C, A, B0, B1) \
    asm volatile("mma.sync.aligned.m16n8k16.row.col.f32.f16.f16.f32 " \
                 "{%0,%1,%2,%3}, {%4,%5,%6,%7}, {%8,%9}, {%0,%1,%2,%3};" \
                 : "+f"((C)[0]), "+f"((C)[1]), "+f"((C)[2]), "+f"((C)[3]) \
                 : "r"((A)[0]), "r"((A)[1]), "r"((A)[2]), "r"((A)[3]), \
                   "r"(B0), "r"(B1))

// ---------------- kernel 1: dequant packed int4 -> fp16 W (wide) ----------------
__global__ void dequant_kernel(const int* __restrict__ packed,
                               const float* __restrict__ scales) {
    size_t i = (size_t)blockIdx.x * blockDim.x + threadIdx.x;   // uint4 index
    const size_t n = (size_t)OUT_DIM * (IN_DIM / 2) / 4;
    if (i >= n) return;
    uint4 p = reinterpret_cast<const uint4*>(packed)[i];
    int row = (int)((i * 4) >> 11);          // IN_DIM/2 = 2048 per row, 4 | 2048
    float s = scales[row];
    uint4 o;
    {
        int v = (int)p.x;
        o.x = h2_as_u32(__floats2half2_rn((float)((v & 15) - 8) * s,
                                          (float)(((v >> 4) & 15) - 8) * s));
        v = (int)p.y;
        o.y = h2_as_u32(__floats2half2_rn((float)((v & 15) - 8) * s,
                                          (float)(((v >> 4) & 15) - 8) * s));
        v = (int)p.z;
        o.z = h2_as_u32(__floats2half2_rn((float)((v & 15) - 8) * s,
                                          (float)(((v >> 4) & 15) - 8) * s));
        v = (int)p.w;
        o.w = h2_as_u32(__floats2half2_rn((float)((v & 15) - 8) * s,
                                          (float)(((v >> 4) & 15) - 8) * s));
    }
    reinterpret_cast<uint4*>(g_Wh)[i] = o;
}

// ---------------- kernel 2: sparse scatter-add (native fp16 atomics) ----------------
__global__ void scatter_kernel(const float* __restrict__ vals,
                               const int* __restrict__ rows,
                               const int* __restrict__ cols, int nnz) {
    int i = blockIdx.x * blockDim.x + threadIdx.x;
    if (i >= nnz) return;
    atomicAdd(&g_Wh[(size_t)rows[i] * IN_DIM + cols[i]], __float2half(vals[i]));
}

// ---------------- kernel 3: convert x -> fp16 (wide) ----------------
__global__ void convert_x_kernel(const float* __restrict__ x) {
    size_t i = (size_t)blockIdx.x * blockDim.x + threadIdx.x;   // 8-elem unit
    const size_t n8 = (size_t)MTOK * IN_DIM / 8;
    if (i >= n8) return;
    float4 v0 = reinterpret_cast<const float4*>(x)[2 * i + 0];
    float4 v1 = reinterpret_cast<const float4*>(x)[2 * i + 1];
    uint4 o;
    o.x = h2_as_u32(__floats2half2_rn(v0.x, v0.y));
    o.y = h2_as_u32(__floats2half2_rn(v0.z, v0.w));
    o.z = h2_as_u32(__floats2half2_rn(v1.x, v1.y));
    o.w = h2_as_u32(__floats2half2_rn(v1.z, v1.w));
    reinterpret_cast<uint4*>(g_Xh)[i] = o;
}

// ---------------- kernel 4: mma.sync fp16 GEMM (fp32 accum) ----------------
// out = Xh * Wh^T. CTA tile 128x128, 8 warps (2x4), warp tile 64x32, K-tile 64
// (4 x k16 sub-steps), 3-stage cp.async pipeline (32KB/stage), 2 CTA/SM.
// ONE barrier + ONE wait_group per K-tile iteration; prefetch issued between
// the kk=0 fragment loads and the kk=0 MMA block (branch-free).
#define KTILE 64
#define A_BYTES 16384
#define STAGE_BYTES 32768
#define N_ITERS (IN_DIM / KTILE)   // 64

#define SWZ(r_, c_) ((r_) * 128 + ((((c_) ^ ((r_) & 7))) << 4))

__global__ void __launch_bounds__(256, 2) gemm_kernel(float* __restrict__ out) {
    extern __shared__ char smem[];
    const int tid  = threadIdx.x;
    const int lane = tid & 31;
    const int w    = tid >> 5;
    const int wm   = w & 1;        // 0..1 : 64-row half (M)
    const int wn   = w >> 1;       // 0..3 : 32-col quarter (N)
    const int mt   = blockIdx.x;   // 0..15
    const int nt   = blockIdx.y;   // 0..85

    float c[4][4][4];
    #pragma unroll
    for (int mi = 0; mi < 4; ++mi)
        #pragma unroll
        for (int ni = 0; ni < 4; ++ni)
            #pragma unroll
            for (int q = 0; q < 4; ++q) c[mi][ni][q] = 0.f;

    const int lr = tid >> 3;             // 0..31
    const int lc = tid & 7;              // chunk 0..7
    const unsigned sbase = smem_u32(smem);

    // hoisted fragment row/column terms (kk-invariant)
    const int arow[4] = { wm * 64 +  0 + (lane & 15), wm * 64 + 16 + (lane & 15),
                          wm * 64 + 32 + (lane & 15), wm * 64 + 48 + (lane & 15) };
    const int acol = lane >> 4;                                   // 0..1
    const int brow[2] = { wn * 32 +  0 + (lane & 7) + ((lane >> 4) << 3),
                          wn * 32 + 16 + (lane & 7) + ((lane >> 4) << 3) };
    const int bcol = (lane >> 3) & 1;                             // 0..1

    const __half* Ab = g_Xh + (size_t)mt * 128 * IN_DIM;
    const __half* Bb = g_Wh + (size_t)nt * 128 * IN_DIM;

    #define LOAD_TILE(it_) do {                                                   \
        int k0_ = (it_) << 6;                                                     \
        unsigned sa_ = sbase + ((it_) % 3) * STAGE_BYTES;                         \
        unsigned sb_ = sa_ + A_BYTES;                                             \
        const __half* ap_ = Ab + k0_ + lc * 8;                                    \
        const __half* bp_ = Bb + k0_ + lc * 8;                                    \
        _Pragma("unroll")                                                         \
        for (int p_ = 0; p_ < 4; ++p_) {                                          \
            int r_ = lr + p_ * 32;                                                \
            CP16(sa_ + SWZ(r_, lc), ap_ + (size_t)r_ * IN_DIM);                   \
            CP16(sb_ + SWZ(r_, lc), bp_ + (size_t)r_ * IN_DIM);                   \
        }                                                                         \
    } while (0)

    #define LOAD_FRAGS(kk_, A_, B_) do {                                          \
        _Pragma("unroll")                                                         \
        for (int mi_ = 0; mi_ < 4; ++mi_)                                         \
            LDSM4((A_)[mi_], sa + SWZ(arow[mi_], 2 * (kk_) + acol));              \
        _Pragma("unroll")                                                         \
        for (int nj_ = 0; nj_ < 2; ++nj_)                                         \
            LDSM4((B_)[nj_], sb + SWZ(brow[nj_], 2 * (kk_) + bcol));              \
    } while (0)

    #define DO_MMAS(A_, B_) do {                                                  \
        _Pragma("unroll")                                                         \
        for (int mi_ = 0; mi_ < 4; ++mi_)                                         \
            _Pragma("unroll")                                                     \
            for (int ni_ = 0; ni_ < 4; ++ni_)                                     \
                MMA16816(c[mi_][ni_], (A_)[mi_],                                  \
                         (B_)[ni_ >> 1][(ni_ & 1) * 2 + 0],                       \
                         (B_)[ni_ >> 1][(ni_ & 1) * 2 + 1]);                      \
    } while (0)

    LOAD_TILE(0);
    asm volatile("cp.async.commit_group;" ::: "memory");
    LOAD_TILE(1);
    asm volatile("cp.async.commit_group;" ::: "memory");

    for (int it = 0; it < N_ITERS; ++it) {
        asm volatile("cp.async.wait_group 1;" ::: "memory");
        __syncthreads();

        unsigned sa = sbase + (it % 3) * STAGE_BYTES;
        unsigned sb = sa + A_BYTES;

        // kk = 0: fragments, then branch-free prefetch, then MMAs
        unsigned a[4][4], b[2][4];
        LOAD_FRAGS(0, a, b);

        if (it + 2 < N_ITERS) LOAD_TILE(it + 2);
        asm volatile("cp.async.commit_group;" ::: "memory");

        DO_MMAS(a, b);

        #pragma unroll
        for (int kk = 1; kk < 4; ++kk) {
            LOAD_FRAGS(kk, a, b);
            DO_MMAS(a, b);
        }
        // no trailing barrier: next iter's top barrier provides ordering
    }

    // ---- epilogue: direct fp32 stores ----
    const int r0 = mt * 128 + wm * 64 + (lane >> 2);
    const int c0 = nt * 128 + wn * 32 + (lane & 3) * 2;
    #pragma unroll
    for (int mi = 0; mi < 4; ++mi) {
        #pragma unroll
        for (int ni = 0; ni < 4; ++ni) {
            size_t rowA = (size_t)(r0 + mi * 16) * OUT_DIM + c0 + ni * 8;
            size_t rowB = rowA + (size_t)8 * OUT_DIM;
            float2 v01; v01.x = c[mi][ni][0]; v01.y = c[mi][ni][1];
            float2 v23; v23.x = c[mi][ni][2]; v23.y = c[mi][ni][3];
            *reinterpret_cast<float2*>(out + rowA) = v01;
            *reinterpret_cast<float2*>(out + rowB) = v23;
        }
    }
}

// ---------------- launcher ----------------
extern "C" void kernel_launch(void* const* d_in, const int* in_sizes, int n_in,
                              void* d_out, int out_size) {
    const float* x      = (const float*)d_in[0];
    const float* scales = (const float*)d_in[1];
    const float* vals   = (const float*)d_in[2];
    const int*   packed = (const int*)d_in[3];
    const int*   rows   = (const int*)d_in[4];
    const int*   cols   = (const int*)d_in[5];
    float* out = (float*)d_out;
    int nnz = in_sizes[2];

    // idempotent, non-stream API: safe under graph capture
    cudaFuncSetAttribute(gemm_kernel,
                         cudaFuncAttributeMaxDynamicSharedMemorySize,
                         3 * STAGE_BYTES);

    {
        size_t n = (size_t)OUT_DIM * (IN_DIM / 2) / 4;
        dequant_kernel<<<(unsigned)((n + 255) / 256), 256>>>(packed, scales);
    }
    scatter_kernel<<<(nnz + 255) / 256, 256>>>(vals, rows, cols, nnz);
    {
        size_t n8 = (size_t)MTOK * IN_DIM / 8;
        convert_x_kernel<<<(unsigned)((n8 + 255) / 256), 256>>>(x);
    }
    {
        dim3 grid(MTOK / 128, OUT_DIM / 128);  // (16, 86); x fastest -> B n-tile L2 reuse
        gemm_kernel<<<grid, 256, 3 * STAGE_BYTES>>>(out);
    }
}